// round 9
// baseline (speedup 1.0000x reference)
#include <cuda_runtime.h>
#include <cuda_bf16.h>
#include <math.h>
#include <float.h>

// Fixed problem shapes
#define BB 32
#define NN 300
#define MM 50
#define NSLOT 10          // columns per lane: lanes 0..11 own 10, lanes 12..31 own 9

#define LAMBDA_POS 5.0
#define LAMBDA_CONF 2.0
#define LAMBDA_NOOBJ 0.5

#define FULLMASK 0xffffffffu

// Fixed-point scale 2^38 (resolution 3.6e-12): headroom for dual accumulation
// even in pathological kick chains (|v| < 2^51, keys<<9 < 2^61).
#define QSCALE 274877906944.0   // 2^38
#define CBIAS  2.0              // makes all quantized costs strictly positive

#define ARR_CAP 400             // termination guarantee for the ARR kick loop

// Cross-block scratch (no cudaMalloc allowed)
__device__ double g_part[BB * 3];
__device__ int    g_done = 0;

__device__ __forceinline__ unsigned long long umin64(unsigned long long a, unsigned long long b) {
    return a < b ? a : b;
}
__device__ __forceinline__ unsigned long long umax64(unsigned long long a, unsigned long long b) {
    return a > b ? a : b;
}
// warp argmin over packed u64 keys (key = (q<<9)|j, q >= 0): two u32 redux
__device__ __forceinline__ unsigned long long warp_min_key(unsigned long long mloc) {
    unsigned hi   = (unsigned)(mloc >> 32);
    unsigned hmin = __reduce_min_sync(FULLMASK, hi);
    unsigned lo   = (hi == hmin) ? (unsigned)mloc : 0xFFFFFFFFu;
    unsigned lmin = __reduce_min_sync(FULLMASK, lo);
    return ((unsigned long long)hmin << 32) | lmin;
}
__device__ __forceinline__ unsigned long long shfl_xor_u64(unsigned long long x, int off) {
    unsigned lo = (unsigned)x, hi = (unsigned)(x >> 32);
    lo = __shfl_xor_sync(FULLMASK, lo, off);
    hi = __shfl_xor_sync(FULLMASK, hi, off);
    return ((unsigned long long)hi << 32) | lo;
}
__device__ __forceinline__ double softplus_d(double x) {
    return fmax(x, 0.0) + log1p(exp(-fabs(x)));
}

// Dynamic smem layout (8-byte entries first)
#define SMEM_QWORDS (MM * NN + NN + NN + MM)
#define QROW_CAP    (MM + ARR_CAP + 8)
#define SMEM_BYTES  (SMEM_QWORDS * 8 + MM * 2 * 4 + (NN + NN + MM + QROW_CAP) * 4)

__global__ void __launch_bounds__(32, 1)
detloss_kernel(const float* __restrict__ pred_c,  // [B,N,2]
               const float* __restrict__ conf,    // [B,N]
               const float* __restrict__ gt_c,    // [B,M,2]
               float* __restrict__ out)           // [5]
{
    const int b    = blockIdx.x;
    const int lane = threadIdx.x;

    const float* pc = pred_c + b * NN * 2;
    const float* cf = conf   + b * NN;
    const float* gc = gt_c   + b * MM * 2;

    extern __shared__ long long dyn[];
    long long* sq   = dyn;                  // [MM][NN] packed cost keys (q<<9)|j
    long long* spq  = sq + MM * NN;         // [NN] exact shortest (q units)
    long long* urq  = spq + NN;             // [NN] u[row4col[j]] cache (q units)
    long long* suq  = urq + NN;             // [MM] dual u (q units)
    float*     sgt  = (float*)(suq + MM);   // [MM*2] staged gt
    int*       pb   = (int*)(sgt + MM * 2); // [NN] pathback
    int*       r4c  = pb + NN;              // [NN] row4col (-1 = free)
    int*       c4r  = r4c + NN;             // [MM] col4row (-1 = unassigned)
    int*       qrow = c4r + MM;             // [QROW_CAP] ARR work queue

    // ---- Stage gt; init state ----
    for (int t = lane; t < MM * 2; t += 32) sgt[t] = gc[t];
    for (int j = lane; j < NN; j += 32) { r4c[j] = -1; urq[j] = 0; }
    for (int m = lane; m < MM; m += 32) { suq[m] = 0; c4r[m] = -1; }
    __syncwarp();

    // ---- Build packed cost keys: q = rn((5*L1 - sigmoid + 2)*2^38) > 0 ----
    // Column j is built AND consumed by lane (j % 32): no sync needed on sq.
    #pragma unroll
    for (int k = 0; k < NSLOT; k++) {
        int j = k * 32 + lane;
        if (j < NN) {
            double x    = (double)cf[j];
            double base = (CBIAS - 1.0 / (1.0 + exp(-x))) * QSCALE;
            double px   = (double)pc[2 * j];
            double py   = (double)pc[2 * j + 1];
            for (int m = 0; m < MM; m++) {
                double dx = fabs(px - (double)sgt[2 * m]);
                double dy = fabs(py - (double)sgt[2 * m + 1]);
                long long q = __double2ll_rn(fma(dx + dy, 5.0 * QSCALE, base));
                sq[m * NN + j] = (q << 9) | (long long)j;
            }
        }
    }

    // per-lane register duals for owned columns (q units, always <= 0)
    long long vq[NSLOT];
    #pragma unroll
    for (int k = 0; k < NSLOT; k++) vq[k] = 0;
    const unsigned validMask = (lane < 12) ? 0x3FFu : 0x1FFu;

    // ==== Phase 1: row reduction + greedy; collisions go to the ARR queue ====
    int tail = 0;   // uniform across warp
    for (int i = 0; i < MM; i++) {
        const long long* crow = sq + i * NN;
        unsigned long long best = ~0ULL;
        #pragma unroll
        for (int k = 0; k < NSLOT; k++) {
            if (validMask & (1u << k)) {
                best = umin64(best, (unsigned long long)crow[k * 32 + lane]);
            }
        }
        unsigned long long mk = warp_min_key(best);
        int       jmin = (int)(mk & 511u);
        long long rmin = (long long)(mk >> 9);
        suq[i] = rmin;                       // same value from all lanes
        if (r4c[jmin] < 0) {
            r4c[jmin] = i;
            c4r[i]    = jmin;
            urq[jmin] = rmin;
        } else {
            qrow[tail] = i;                  // uniform write
            tail++;
        }
    }
    __syncwarp();

    // ==== Phase 1b: augmenting row reduction (LAPJV) ====
    // For unassigned row i: two smallest reduced costs mu1@j1, mu2.
    // u[i]=mu2; v[j1]-=(mu2-mu1); i takes j1, kicking its owner back to queue.
    // Maintains c-u-v >= 0 exactly and CS on matched edges.
    {
        int head = 0, iters = 0;
        while (head < tail && iters < ARR_CAP) {
            iters++;
            int i = qrow[head]; head++;          // uniform broadcast read
            const long long* crow = sq + i * NN;

            unsigned long long k1 = ~0ULL, k2 = ~0ULL;
            #pragma unroll
            for (int k = 0; k < NSLOT; k++) {
                if (validMask & (1u << k)) {
                    unsigned long long ck =
                        (unsigned long long)(crow[k * 32 + lane] - (vq[k] << 9));
                    if (ck < k1) { k2 = k1; k1 = ck; }
                    else if (ck < k2) { k2 = ck; }
                }
            }
            // warp merge of sorted pairs (keys unique: j packed in low bits)
            #pragma unroll
            for (int off = 16; off; off >>= 1) {
                unsigned long long o1 = shfl_xor_u64(k1, off);
                unsigned long long o2 = shfl_xor_u64(k2, off);
                unsigned long long m1 = umin64(k1, o1);
                unsigned long long m2 = umin64(umax64(k1, o1), umin64(k2, o2));
                k1 = m1; k2 = m2;
            }
            int       j1  = (int)(k1 & 511u);
            long long mu1 = (long long)(k1 >> 9);
            long long mu2 = (long long)(k2 >> 9);

            if ((j1 & 31) == lane) vq[j1 >> 5] -= (mu2 - mu1);  // owner lane

            int kk = r4c[j1];                    // uniform read (before writes)
            suq[i]  = mu2;
            urq[j1] = mu2;
            r4c[j1] = i;
            c4r[i]  = j1;
            if (kk >= 0) {
                c4r[kk] = -1;
                qrow[tail] = kk;                 // uniform write
                tail++;
                if (tail >= QROW_CAP) break;     // safety (cannot happen w/ cap)
            }
            __syncwarp();
        }
    }
    __syncwarp();

    // ==== Phase 2: shortest augmenting path for any remaining rows ====
    for (int cur = 0; cur < MM; cur++) {
        if (c4r[cur] >= 0) continue;

        unsigned long long skey[NSLOT];
        #pragma unroll
        for (int k = 0; k < NSLOT; k++) skey[k] = ~0ULL;
        unsigned rem = validMask;
        unsigned remRound = 0;
        unsigned long long SR = 1ULL << cur;

        int       i    = cur;
        long long uiq  = suq[cur];
        long long minq = 0;
        int       sink;

        while (true) {
            long long pq = minq - uiq;
            const long long* crow = sq + i * NN;

            #pragma unroll
            for (int k = 0; k < NSLOT; k++) {
                if (rem & (1u << k)) {
                    int j = k * 32 + lane;
                    long long off = (pq - vq[k]) << 9;
                    unsigned long long ck = (unsigned long long)(crow[j] + off);
                    if (ck < skey[k]) {
                        skey[k] = ck;
                        spq[j]  = (long long)(ck >> 9);
                        pb[j]   = i;
                    }
                }
            }
            unsigned long long a0 = umin64(skey[0], skey[1]);
            unsigned long long a1 = umin64(skey[2], skey[3]);
            unsigned long long a2 = umin64(skey[4], skey[5]);
            unsigned long long a3 = umin64(skey[6], skey[7]);
            unsigned long long a4 = umin64(skey[8], skey[9]);
            unsigned long long mloc = umin64(umin64(umin64(a0, a1), umin64(a2, a3)), a4);

            unsigned long long mk = warp_min_key(mloc);
            int jst = (int)(mk & 511u);
            minq    = (long long)(mk >> 9);

            if ((jst & 31) == lane) {        // owner retires its column locally
                int slot = jst >> 5;
                rem      &= ~(1u << slot);
                remRound |=  (1u << slot);
                #pragma unroll
                for (int k = 0; k < NSLOT; k++) if (k == slot) skey[k] = ~0ULL;
            }

            int       rr = r4c[jst];
            long long uu = urq[jst];
            if (rr < 0) { sink = jst; break; }
            i   = rr;
            uiq = uu;
            SR |= 1ULL << i;
        }

        __syncwarp();

        // dual updates (exact integer)
        for (int m = lane; m < MM; m += 32) {
            if (m == cur) {
                suq[m] += minq;
            } else if ((SR >> m) & 1) {
                suq[m] += minq - spq[c4r[m]];
            }
        }
        #pragma unroll
        for (int k = 0; k < NSLOT; k++) {
            if (remRound & (1u << k)) {
                int j = k * 32 + lane;
                vq[k] -= (minq - spq[j]);
            }
        }
        __syncwarp();

        // augment (lane 0)
        if (lane == 0) {
            int j = sink;
            while (true) {
                int ii = pb[j];
                r4c[j] = ii;
                int t = c4r[ii];
                c4r[ii] = j;
                j = t;
                if (ii == cur) break;
            }
        }
        __syncwarp();

        // refresh urq cache for matched columns
        for (int m = lane; m < MM; m += 32) {
            int jm = c4r[m];
            if (jm >= 0) urq[jm] = suq[m];
        }
        __syncwarp();
    }

    // ==== Loss partials (exact fp64 from original inputs) ====
    double pos = 0.0, obj = 0.0, noobj = 0.0;
    for (int m = lane; m < MM; m += 32) {
        int j = c4r[m];
        double dx = fabs((double)pc[2 * j]     - (double)sgt[2 * m]);
        double dy = fabs((double)pc[2 * j + 1] - (double)sgt[2 * m + 1]);
        pos += dx + dy;
        obj += softplus_d(-(double)cf[j]);
    }
    #pragma unroll
    for (int k = 0; k < NSLOT; k++) {
        int j = k * 32 + lane;
        if (j < NN && r4c[j] < 0)
            noobj += softplus_d((double)cf[j]);
    }
    #pragma unroll
    for (int off = 16; off; off >>= 1) {
        pos   += __shfl_xor_sync(FULLMASK, pos,   off);
        obj   += __shfl_xor_sync(FULLMASK, obj,   off);
        noobj += __shfl_xor_sync(FULLMASK, noobj, off);
    }
    int islast = 0;
    if (lane == 0) {
        g_part[b * 3 + 0] = pos   / (double)(MM * 2);
        g_part[b * 3 + 1] = obj   / (double)MM;
        g_part[b * 3 + 2] = noobj / (double)(NN - MM);
        __threadfence();
        int t = atomicAdd(&g_done, 1);
        islast = (t == BB - 1);
    }
    islast = __shfl_sync(FULLMASK, islast, 0);

    if (islast) {  // fused finalize: last block reduces the 32 partials
        __threadfence();
        double p = 0.0, o = 0.0, q = 0.0;
        if (lane < BB) {
            p = g_part[lane * 3 + 0];
            o = g_part[lane * 3 + 1];
            q = g_part[lane * 3 + 2];
        }
        #pragma unroll
        for (int off = 16; off; off >>= 1) {
            p += __shfl_xor_sync(FULLMASK, p, off);
            o += __shfl_xor_sync(FULLMASK, o, off);
            q += __shfl_xor_sync(FULLMASK, q, off);
        }
        if (lane == 0) {
            float lp = (float)(LAMBDA_POS   * p / (double)BB);
            float lo = (float)(LAMBDA_CONF  * o / (double)BB);
            float ln = (float)(LAMBDA_NOOBJ * q / (double)BB);
            out[0] = lp;
            out[1] = lo;
            out[2] = ln;
            out[3] = lp + lo + ln;
            out[4] = (float)MM;
            g_done = 0;   // self-reset for next graph replay
        }
    }
}

extern "C" void kernel_launch(void* const* d_in, const int* in_sizes, int n_in,
                              void* d_out, int out_size)
{
    const float* pred_c = (const float*)d_in[0];
    const float* conf   = (const float*)d_in[2];
    const float* gt_c   = (const float*)d_in[3];
    float* out = (float*)d_out;

    cudaFuncSetAttribute(detloss_kernel,
                         cudaFuncAttributeMaxDynamicSharedMemorySize, SMEM_BYTES);
    detloss_kernel<<<BB, 32, SMEM_BYTES>>>(pred_c, conf, gt_c, out);
}

// round 10
// speedup vs baseline: 1.6001x; 1.6001x over previous
#include <cuda_runtime.h>
#include <cuda_bf16.h>
#include <math.h>
#include <float.h>

// Fixed problem shapes
#define BB 32
#define NN 300
#define MM 50
#define NSLOT 10          // columns per lane: lanes 0..11 own 10, lanes 12..31 own 9

#define LAMBDA_POS 5.0
#define LAMBDA_CONF 2.0
#define LAMBDA_NOOBJ 0.5

#define FULLMASK 0xffffffffu

// Fixed-point scale 2^38 (resolution 3.6e-12); bias +2 keeps all costs > 0.
#define QSCALE 274877906944.0   // 2^38
#define CBIAS  2.0

// Cross-block scratch (no cudaMalloc allowed)
__device__ double g_part[BB * 3];
__device__ int    g_done = 0;

__device__ __forceinline__ unsigned long long umin64(unsigned long long a, unsigned long long b) {
    return a < b ? a : b;
}
__device__ __forceinline__ unsigned long long umax64(unsigned long long a, unsigned long long b) {
    return a > b ? a : b;
}
// warp argmin over packed u64 keys (key = (q<<9)|j, q >= 0): two u32 redux
__device__ __forceinline__ unsigned long long warp_min_key(unsigned long long mloc) {
    unsigned hi   = (unsigned)(mloc >> 32);
    unsigned hmin = __reduce_min_sync(FULLMASK, hi);
    unsigned lo   = (hi == hmin) ? (unsigned)mloc : 0xFFFFFFFFu;
    unsigned lmin = __reduce_min_sync(FULLMASK, lo);
    return ((unsigned long long)hmin << 32) | lmin;
}
__device__ __forceinline__ unsigned long long shfl_xor_u64(unsigned long long x, int off) {
    unsigned lo = (unsigned)x, hi = (unsigned)(x >> 32);
    lo = __shfl_xor_sync(FULLMASK, lo, off);
    hi = __shfl_xor_sync(FULLMASK, hi, off);
    return ((unsigned long long)hi << 32) | lo;
}
__device__ __forceinline__ double softplus_d(double x) {
    return fmax(x, 0.0) + log1p(exp(-fabs(x)));
}

// Dynamic smem layout (8-byte entries first)
#define SMEM_QWORDS (MM * NN + NN + NN + MM)
#define SMEM_BYTES  (SMEM_QWORDS * 8 + MM * 2 * 4 + (NN + NN + MM) * 4)

__global__ void __launch_bounds__(32, 1)
detloss_kernel(const float* __restrict__ pred_c,  // [B,N,2]
               const float* __restrict__ conf,    // [B,N]
               const float* __restrict__ gt_c,    // [B,M,2]
               float* __restrict__ out)           // [5]
{
    const int b    = blockIdx.x;
    const int lane = threadIdx.x;

    const float* pc = pred_c + b * NN * 2;
    const float* cf = conf   + b * NN;
    const float* gc = gt_c   + b * MM * 2;

    extern __shared__ long long dyn[];
    long long* sq   = dyn;                  // [MM][NN] packed cost keys (q<<9)|j
    long long* spq  = sq + MM * NN;         // [NN] shortest at removal (q units)
    long long* urq  = spq + NN;             // [NN] u[row4col[j]] cache (q units)
    long long* suq  = urq + NN;             // [MM] dual u (q units)
    float*     sgt  = (float*)(suq + MM);   // [MM*2] staged gt
    int*       pb   = (int*)(sgt + MM * 2); // [NN] pathback
    int*       r4c  = pb + NN;              // [NN] row4col (-1 = free)
    int*       c4r  = r4c + NN;             // [MM] col4row (-1 = unassigned)

    // ---- Stage gt; init state ----
    for (int t = lane; t < MM * 2; t += 32) sgt[t] = gc[t];
    for (int j = lane; j < NN; j += 32) { r4c[j] = -1; urq[j] = 0; }
    for (int m = lane; m < MM; m += 32) { suq[m] = 0; c4r[m] = -1; }
    __syncwarp();

    // ---- Build packed cost keys: q = rn((5*L1 - sigmoid + 2)*2^38) > 0 ----
    // Column j is built AND consumed by lane (j % 32): no sync needed on sq.
    #pragma unroll
    for (int k = 0; k < NSLOT; k++) {
        int j = k * 32 + lane;
        if (j < NN) {
            double x    = (double)cf[j];
            double base = (CBIAS - 1.0 / (1.0 + exp(-x))) * QSCALE;
            double px   = (double)pc[2 * j];
            double py   = (double)pc[2 * j + 1];
            for (int m = 0; m < MM; m++) {
                double dx = fabs(px - (double)sgt[2 * m]);
                double dy = fabs(py - (double)sgt[2 * m + 1]);
                long long q = __double2ll_rn(fma(dx + dy, 5.0 * QSCALE, base));
                sq[m * NN + j] = (q << 9) | (long long)j;
            }
        }
    }

    // per-lane register duals for owned columns (q units, <= 0)
    long long vq[NSLOT];
    #pragma unroll
    for (int k = 0; k < NSLOT; k++) vq[k] = 0;
    const unsigned validMask = (lane < 12) ? 0x3FFu : 0x1FFu;

    // ==== Phase 1: greedy assignment WITH fused reduction transfer ====
    // Two smallest reduced costs mu1@j1, mu2 per row (w.r.t. current v).
    //  - j1 free:  assign; u[i]=mu2, v[j1] += (mu1-mu2)  (exact CS, feasible,
    //              makes matched columns strictly unattractive for Phase 2)
    //  - j1 taken: leave row for Phase 2 with tight feasible u[i]=mu1.
    for (int i = 0; i < MM; i++) {
        const long long* crow = sq + i * NN;
        unsigned long long k1 = ~0ULL, k2 = ~0ULL;
        #pragma unroll
        for (int k = 0; k < NSLOT; k++) {
            if (validMask & (1u << k)) {
                unsigned long long ck =
                    (unsigned long long)(crow[k * 32 + lane] - (vq[k] << 9));
                if (ck < k1) { k2 = k1; k1 = ck; }
                else if (ck < k2) { k2 = ck; }
            }
        }
        // warp merge of per-lane sorted pairs (keys unique: j in low bits)
        #pragma unroll
        for (int off = 16; off; off >>= 1) {
            unsigned long long o1 = shfl_xor_u64(k1, off);
            unsigned long long o2 = shfl_xor_u64(k2, off);
            unsigned long long m1 = umin64(k1, o1);
            unsigned long long m2 = umin64(umax64(k1, o1), umin64(k2, o2));
            k1 = m1; k2 = m2;
        }
        int       j1  = (int)(k1 & 511u);
        long long mu1 = (long long)(k1 >> 9);
        long long mu2 = (long long)(k2 >> 9);

        if (r4c[j1] < 0) {                    // uniform branch (smem broadcast)
            r4c[j1] = i;
            c4r[i]  = j1;
            suq[i]  = mu2;
            urq[j1] = mu2;
            if ((j1 & 31) == lane) vq[j1 >> 5] += (mu1 - mu2);   // v[j1]=c-mu2
        } else {
            suq[i] = mu1;
        }
    }
    __syncwarp();

    // ==== Phase 2: shortest augmenting path (all-integer) ====
    for (int cur = 0; cur < MM; cur++) {
        if (c4r[cur] >= 0) continue;

        unsigned long long skey[NSLOT];
        int pbk[NSLOT];
        #pragma unroll
        for (int k = 0; k < NSLOT; k++) { skey[k] = ~0ULL; pbk[k] = 0; }
        unsigned rem = validMask;
        unsigned remRound = 0;
        unsigned long long SR = 1ULL << cur;

        int       i    = cur;
        long long uiq  = suq[cur];
        long long minq = 0;
        int       sink;

        while (true) {
            long long pq = minq - uiq;
            const long long* crow = sq + i * NN;

            // relax: pure register updates (no smem stores)
            #pragma unroll
            for (int k = 0; k < NSLOT; k++) {
                if (rem & (1u << k)) {
                    int j = k * 32 + lane;
                    long long off = (pq - vq[k]) << 9;
                    unsigned long long ck = (unsigned long long)(crow[j] + off);
                    if (ck < skey[k]) { skey[k] = ck; pbk[k] = i; }
                }
            }
            unsigned long long a0 = umin64(skey[0], skey[1]);
            unsigned long long a1 = umin64(skey[2], skey[3]);
            unsigned long long a2 = umin64(skey[4], skey[5]);
            unsigned long long a3 = umin64(skey[6], skey[7]);
            unsigned long long a4 = umin64(skey[8], skey[9]);
            unsigned long long mloc = umin64(umin64(umin64(a0, a1), umin64(a2, a3)), a4);

            unsigned long long mk = warp_min_key(mloc);
            int jst = (int)(mk & 511u);
            minq    = (long long)(mk >> 9);

            if (lane == 0) spq[jst] = minq;   // shortest value at removal
            if ((jst & 31) == lane) {         // owner retires its column
                int slot = jst >> 5;
                rem      &= ~(1u << slot);
                remRound |=  (1u << slot);
                #pragma unroll
                for (int k = 0; k < NSLOT; k++) {
                    if (k == slot) { skey[k] = ~0ULL; pb[jst] = pbk[k]; }
                }
            }

            int       rr = r4c[jst];
            long long uu = urq[jst];
            if (rr < 0) { sink = jst; break; }
            i   = rr;
            uiq = uu;
            SR |= 1ULL << i;
        }

        __syncwarp();   // make spq/pb visible

        // dual updates (exact integer)
        for (int m = lane; m < MM; m += 32) {
            if (m == cur) {
                suq[m] += minq;
            } else if ((SR >> m) & 1) {
                suq[m] += minq - spq[c4r[m]];
            }
        }
        #pragma unroll
        for (int k = 0; k < NSLOT; k++) {
            if (remRound & (1u << k)) {
                int j = k * 32 + lane;
                vq[k] -= (minq - spq[j]);
            }
        }
        __syncwarp();

        // augment (lane 0)
        if (lane == 0) {
            int j = sink;
            while (true) {
                int ii = pb[j];
                r4c[j] = ii;
                int t = c4r[ii];
                c4r[ii] = j;
                j = t;
                if (ii == cur) break;
            }
        }
        __syncwarp();

        // refresh urq cache for matched columns
        for (int m = lane; m < MM; m += 32) {
            int jm = c4r[m];
            if (jm >= 0) urq[jm] = suq[m];
        }
        __syncwarp();
    }

    // ==== Loss partials (exact fp64 from original inputs) ====
    double pos = 0.0, obj = 0.0, noobj = 0.0;
    for (int m = lane; m < MM; m += 32) {
        int j = c4r[m];
        double dx = fabs((double)pc[2 * j]     - (double)sgt[2 * m]);
        double dy = fabs((double)pc[2 * j + 1] - (double)sgt[2 * m + 1]);
        pos += dx + dy;
        obj += softplus_d(-(double)cf[j]);
    }
    #pragma unroll
    for (int k = 0; k < NSLOT; k++) {
        int j = k * 32 + lane;
        if (j < NN && r4c[j] < 0)
            noobj += softplus_d((double)cf[j]);
    }
    #pragma unroll
    for (int off = 16; off; off >>= 1) {
        pos   += __shfl_xor_sync(FULLMASK, pos,   off);
        obj   += __shfl_xor_sync(FULLMASK, obj,   off);
        noobj += __shfl_xor_sync(FULLMASK, noobj, off);
    }
    int islast = 0;
    if (lane == 0) {
        g_part[b * 3 + 0] = pos   / (double)(MM * 2);
        g_part[b * 3 + 1] = obj   / (double)MM;
        g_part[b * 3 + 2] = noobj / (double)(NN - MM);
        __threadfence();
        int t = atomicAdd(&g_done, 1);
        islast = (t == BB - 1);
    }
    islast = __shfl_sync(FULLMASK, islast, 0);

    if (islast) {  // fused finalize
        __threadfence();
        double p = 0.0, o = 0.0, q = 0.0;
        if (lane < BB) {
            p = g_part[lane * 3 + 0];
            o = g_part[lane * 3 + 1];
            q = g_part[lane * 3 + 2];
        }
        #pragma unroll
        for (int off = 16; off; off >>= 1) {
            p += __shfl_xor_sync(FULLMASK, p, off);
            o += __shfl_xor_sync(FULLMASK, o, off);
            q += __shfl_xor_sync(FULLMASK, q, off);
        }
        if (lane == 0) {
            float lp = (float)(LAMBDA_POS   * p / (double)BB);
            float lo = (float)(LAMBDA_CONF  * o / (double)BB);
            float ln = (float)(LAMBDA_NOOBJ * q / (double)BB);
            out[0] = lp;
            out[1] = lo;
            out[2] = ln;
            out[3] = lp + lo + ln;
            out[4] = (float)MM;
            g_done = 0;   // self-reset for next graph replay
        }
    }
}

extern "C" void kernel_launch(void* const* d_in, const int* in_sizes, int n_in,
                              void* d_out, int out_size)
{
    const float* pred_c = (const float*)d_in[0];
    const float* conf   = (const float*)d_in[2];
    const float* gt_c   = (const float*)d_in[3];
    float* out = (float*)d_out;

    cudaFuncSetAttribute(detloss_kernel,
                         cudaFuncAttributeMaxDynamicSharedMemorySize, SMEM_BYTES);
    detloss_kernel<<<BB, 32, SMEM_BYTES>>>(pred_c, conf, gt_c, out);
}